// round 9
// baseline (speedup 1.0000x reference)
#include <cuda_runtime.h>
#include <cuda_fp16.h>
#include <cstdint>
#include <cstddef>

#define BATCH   8
#define NODES   2048
#define IN_DIM  64
#define HEADS   4
#define OUTD    32
#define UDIM    1024
#define NNB     32
#define NTILES  2048     // 512 n-tiles x 4 u-quarters

// scratch: pre-split fp16 hi/lo per head: [h*64 + d] = hi, [h*64+32+d] = lo
__device__ __half g_Qh[BATCH * NODES * 256];   // Q pre-scaled by 1/sqrt(32)
__device__ __half g_Kh[BATCH * UDIM  * 256];
__device__ float  g_S [BATCH * NODES * UDIM];  // scores (L2-hot)
__device__ int    g_ctr;                       // persistent tile queue

#define CP16(dst, src) asm volatile("cp.async.cg.shared.global [%0], [%1], 16;" :: "r"(dst), "l"(src))
#define CPCOMMIT()     asm volatile("cp.async.commit_group;" ::: "memory")
#define CPWAIT0()      asm volatile("cp.async.wait_group 0;" ::: "memory")

__device__ __forceinline__ uint32_t smem_u32(const void* p) {
    uint32_t a;
    asm("{ .reg .u64 t; cvta.to.shared.u64 t, %1; cvt.u32.u64 %0, t; }" : "=r"(a) : "l"(p));
    return a;
}

// ---------------------------------------------------------------------------
// Kernel 1: QK projection + fp16 hi/lo split (R7-proven). Resets tile queue.
// ---------------------------------------------------------------------------
__global__ void __launch_bounds__(128) qk_kernel(
    const float* __restrict__ x,
    const float* __restrict__ Wq, const float* __restrict__ bq,
    const float* __restrict__ Wk, const float* __restrict__ bk)
{
    __shared__ float xs[16][64];

    if (blockIdx.x == 0 && threadIdx.x == 0) g_ctr = 0;

    const bool isK = (blockIdx.x >= 1024);
    int b, row0;
    const float* W; const float* bias;
    if (!isK) { b = blockIdx.x >> 7;             row0 = (blockIdx.x & 127) << 4; W = Wq; bias = bq; }
    else      { int id = blockIdx.x - 1024; b = id >> 6; row0 = (id & 63) << 4;  W = Wk; bias = bk; }

    const int c = threadIdx.x;
    const float* xb = x + ((size_t)b * NODES + row0) * IN_DIM;
    for (int k = threadIdx.x; k < 16 * 64; k += 128)
        xs[k >> 6][k & 63] = xb[k];

    float4 w[16];
    const float4* Wr = (const float4*)(W + (size_t)c * IN_DIM);
#pragma unroll
    for (int i = 0; i < 16; i++) w[i] = Wr[i];
    const float bb = bias[c];
    __syncthreads();

    const float scale = isK ? 1.0f : 0.17677669529663687f;
    const int col = ((c >> 5) << 6) + (c & 31);              // h*64 + d
    __half* dst = (isK ? g_Kh : g_Qh) +
                  ((size_t)b * (isK ? UDIM : NODES) + row0) * 256;

#pragma unroll
    for (int r = 0; r < 16; r++) {
        const float4* xr = (const float4*)xs[r];
        float a0 = 0.f, a1 = 0.f, a2 = 0.f, a3 = 0.f;
#pragma unroll
        for (int i = 0; i < 4; i++) {
            float4 v0 = xr[i],     v1 = xr[4 + i];
            float4 v2 = xr[8 + i], v3 = xr[12 + i];
            a0 += v0.x * w[i].x      + v0.y * w[i].y      + v0.z * w[i].z      + v0.w * w[i].w;
            a1 += v1.x * w[4 + i].x  + v1.y * w[4 + i].y  + v1.z * w[4 + i].z  + v1.w * w[4 + i].w;
            a2 += v2.x * w[8 + i].x  + v2.y * w[8 + i].y  + v2.z * w[8 + i].z  + v2.w * w[8 + i].w;
            a3 += v3.x * w[12 + i].x + v3.y * w[12 + i].y + v3.z * w[12 + i].z + v3.w * w[12 + i].w;
        }
        float acc = (bb + (a0 + a1) + (a2 + a3)) * scale;
        __half hh = __float2half_rn(acc);
        float  lo = acc - __half2float(hh);
        dst[(size_t)r * 256 + col]      = hh;
        dst[(size_t)r * 256 + col + 32] = __float2half_rn(lo);
    }
}

// ---------------------------------------------------------------------------
// Kernel 2: persistent score kernel, 444 blocks (3/SM target), 256 threads.
// Tile queue: 2048 tiles (32n x 256u), each = 8 chunks of 32u.
// 8 warps = 2n x 4u; warp tile 16n x 8u. A frags via ldmatrix per chunk
// (not cached -> ~80 regs -> 3 blocks/SM). 3 combos hh + hl + lh.
// us==0 tiles zero-fill their 32 output rows (hidden under compute).
// ---------------------------------------------------------------------------
#define SKROW   528
#define SMQ     0                      // 32*528 = 16896
#define SMK     16896                  // 2 * 32*528 = 33792
#define KBUF    (32 * SKROW)
#define SMLP    50688                  // 20 floats mlp + tile id
#define SMEMSZ  50816

__device__ __forceinline__ void mma_f16(float* c, const uint32_t* a, const uint32_t* b) {
    asm volatile("mma.sync.aligned.m16n8k16.row.col.f32.f16.f16.f32 "
        "{%0,%1,%2,%3}, {%4,%5,%6,%7}, {%8,%9}, {%0,%1,%2,%3};"
        : "+f"(c[0]), "+f"(c[1]), "+f"(c[2]), "+f"(c[3])
        : "r"(a[0]), "r"(a[1]), "r"(a[2]), "r"(a[3]), "r"(b[0]), "r"(b[1]));
}
__device__ __forceinline__ void ldsm_x4(uint32_t* r, uint32_t addr) {
    asm volatile("ldmatrix.sync.aligned.m8n8.x4.shared.b16 {%0,%1,%2,%3}, [%4];"
        : "=r"(r[0]), "=r"(r[1]), "=r"(r[2]), "=r"(r[3]) : "r"(addr));
}

__device__ __forceinline__ void fillK_async(uint32_t smb, int b, int ustart, int buf, int tid) {
    const char* src = (const char*)(g_Kh + ((size_t)(b * UDIM + ustart)) * 256);
    const uint32_t dst = smb + SMK + buf * KBUF;
#pragma unroll
    for (int it = 0; it < 4; it++) {
        int idx = it * 256 + tid;            // 32 rows x 32 x 16B
        int row = idx >> 5, j = idx & 31;
        CP16(dst + row * SKROW + j * 16, src + row * 512 + j * 16);
    }
}

__global__ void __launch_bounds__(256, 3) score_kernel(
    const float* __restrict__ mlp_w, const float* __restrict__ mlp_b,
    float* __restrict__ out)
{
    extern __shared__ __align__(16) char sm[];
    const uint32_t smb = smem_u32(sm);
    const int tid = threadIdx.x, lane = tid & 31, wid = tid >> 5;
    const int wr0 = (wid & 1) << 4;           // warp n-offset (0/16)
    const int uw0 = (wid >> 1) << 3;          // warp u-offset in chunk (0..24)

    float* smlp = (float*)(sm + SMLP);
    int*  stile = (int*)(sm + SMLP + 80);
    if (tid < 16) smlp[tid] = mlp_w[tid];
    if (tid < 4)  smlp[16 + tid] = mlp_b[tid];

    // ldmatrix source addresses (fixed per thread, relative bases)
    const uint32_t qoff = (uint32_t)((wr0 + (lane & 15)) * SKROW + ((lane >> 4) << 4));
    const uint32_t koff = (uint32_t)((uw0 + (lane & 7)) * SKROW + ((lane >> 3) << 4));

    for (;;) {
        if (tid == 0) *stile = atomicAdd(&g_ctr, 1);
        __syncthreads();                       // publishes stile, frees smem
        const int t = *stile;
        if (t >= NTILES) break;
        const int nt = t >> 2, us = t & 3;
        const int b  = nt >> 6;
        const int n0 = (nt & 63) << 5;
        const int u0 = us << 8;

        // stage Q tile (32 rows x 512B) + K chunk 0
        {
            const char* qsrc = (const char*)(g_Qh + ((size_t)(b * NODES + n0)) * 256);
#pragma unroll
            for (int it = 0; it < 4; it++) {
                int idx = it * 256 + tid;
                int row = idx >> 5, j = idx & 31;
                CP16(smb + SMQ + row * SKROW + j * 16, qsrc + row * 512 + j * 16);
            }
        }
        fillK_async(smb, b, u0, 0, tid);
        CPCOMMIT();
        CPWAIT0();
        __syncthreads();
        fillK_async(smb, b, u0 + 32, 1, tid);   // prefetch chunk 1
        CPCOMMIT();

        for (int ck = 0; ck < 8; ck++) {
            const int buf = ck & 1;
            if (ck > 0) {
                CPWAIT0();
                __syncthreads();
                if (ck + 1 < 8) { fillK_async(smb, b, u0 + (ck + 1) * 32, buf ^ 1, tid); CPCOMMIT(); }
            }

            // us==0 tiles zero 4 of their 32 output rows per chunk
            if (us == 0) {
                float4* zrow = (float4*)(out + ((size_t)(b * NODES + n0 + ck * 4 + (tid >> 6))) * NODES);
                const float4 z4 = make_float4(0.f, 0.f, 0.f, 0.f);
#pragma unroll
                for (int i = 0; i < 8; i++) zrow[i * 64 + (tid & 63)] = z4;
            }

            float acc[4][4];                   // [head][frag], 16n x 8u
#pragma unroll
            for (int h = 0; h < 4; h++)
#pragma unroll
                for (int j = 0; j < 4; j++) acc[h][j] = 0.f;

            const uint32_t qb = smb + SMQ + qoff;
            const uint32_t kb = smb + SMK + buf * KBUF + koff;
#pragma unroll
            for (int h = 0; h < 4; h++) {
                uint32_t ah0[4], ah1[4], al0[4], al1[4], bh[4], bl[4];
                ldsm_x4(ah0, qb + h * 128);          // A hi k0-15
                ldsm_x4(ah1, qb + h * 128 + 32);     // A hi k16-31
                ldsm_x4(al0, qb + h * 128 + 64);     // A lo k0-15
                ldsm_x4(al1, qb + h * 128 + 96);     // A lo k16-31
                ldsm_x4(bh,  kb + h * 128);          // B hi k0-31
                ldsm_x4(bl,  kb + h * 128 + 64);     // B lo k0-31
                mma_f16(acc[h], ah0, bh);            // hh s0
                mma_f16(acc[h], ah0, bl);            // hl s0
                mma_f16(acc[h], al0, bh);            // lh s0
                mma_f16(acc[h], ah1, bh + 2);        // hh s1
                mma_f16(acc[h], ah1, bl + 2);        // hl s1
                mma_f16(acc[h], al1, bh + 2);        // lh s1
            }

            // epilogue: head mix + relu + residual -> g_S
            float s_[4];
#pragma unroll
            for (int j = 0; j < 4; j++) {
                float a0 = acc[0][j], a1 = acc[1][j];
                float a2 = acc[2][j], a3 = acc[3][j];
                float s = a0 + a1 + a2 + a3;
#pragma unroll
                for (int o = 0; o < 4; o++) {
                    float z = fmaf(smlp[o * 4], a0, fmaf(smlp[o * 4 + 1], a1,
                              fmaf(smlp[o * 4 + 2], a2, fmaf(smlp[o * 4 + 3], a3, smlp[16 + o]))));
                    s += fmaxf(z, 0.f);
                }
                s_[j] = s;
            }
            float* sg = g_S + ((size_t)(b * NODES + n0 + wr0 + (lane >> 2))) * UDIM
                        + u0 + ck * 32 + uw0 + (lane & 3) * 2;
            *(float2*)sg              = make_float2(s_[0], s_[1]);
            *(float2*)(sg + 8 * UDIM) = make_float2(s_[2], s_[3]);
        }
        __syncthreads();   // all warps done with smem before next tile restage
    }
}

// ---------------------------------------------------------------------------
// Kernel 3: top-32 per row via radix select (proven). 1 warp per row.
// Rows were pre-zeroed by score_kernel; this only selects + scatters.
// ---------------------------------------------------------------------------
__global__ void __launch_bounds__(256) topk_kernel(float* __restrict__ out)
{
    const int w = threadIdx.x >> 5, lane = threadIdx.x & 31;
    const int row = blockIdx.x * 8 + w;
    __shared__ unsigned hist[8][256];
    __shared__ unsigned tie_idx[8][64];
    __shared__ unsigned found[8][2];
    __shared__ unsigned tie_cnt[8];

    const float* srow = g_S + (size_t)row * UDIM;
    float    vals[32];
    unsigned keys[32];
#pragma unroll
    for (int j = 0; j < 32; j++) {
        float v = srow[j * 32 + lane];
        vals[j] = v;
        unsigned u = __float_as_uint(v);
        keys[j] = u ^ (((unsigned)((int)u >> 31)) | 0x80000000u);
    }

    unsigned prefix = 0;
    int needed = NNB;
    for (int shift = 24; shift >= 0; shift -= 8) {
        for (int t = lane; t < 256; t += 32) hist[w][t] = 0;
        __syncwarp();
        const unsigned hm = (shift == 24) ? 0u : (0xFFFFFFFFu << (shift + 8));
#pragma unroll
        for (int j = 0; j < 32; j++)
            if (((keys[j] ^ prefix) & hm) == 0)
                atomicAdd(&hist[w][(keys[j] >> shift) & 255], 1u);
        __syncwarp();
        unsigned s = 0;
#pragma unroll
        for (int t = 0; t < 8; t++) s += hist[w][lane * 8 + t];
        unsigned rs = s;
#pragma unroll
        for (int off = 1; off < 32; off <<= 1) {
            unsigned v = __shfl_down_sync(0xffffffffu, rs, off);
            if (lane + off < 32) rs += v;
        }
        unsigned acc = rs - s;            // keys in strictly-higher buckets
        for (int t = 7; t >= 0; t--) {
            unsigned c = hist[w][lane * 8 + t];
            if ((int)acc < needed && needed <= (int)(acc + c)) {
                found[w][0] = (unsigned)(lane * 8 + t);
                found[w][1] = acc;
            }
            acc += c;
        }
        __syncwarp();
        prefix |= found[w][0] << shift;
        needed -= (int)found[w][1];
        __syncwarp();
    }

    const int b = row >> 11, n = row & 2047;
    float* orow = out + ((size_t)b * NODES + n) * (size_t)NODES;
    if (lane == 0) tie_cnt[w] = 0;
    __syncwarp();
#pragma unroll
    for (int j = 0; j < 32; j++) {
        if (keys[j] > prefix) orow[j * 32 + lane] = vals[j];
        else if (keys[j] == prefix) {
            unsigned p = atomicAdd(&tie_cnt[w], 1u);
            if (p < 64) tie_idx[w][p] = (unsigned)(j * 32 + lane);
        }
    }
    __syncwarp();
    if (lane == 0) {
        int cnt = tie_cnt[w] < 64 ? (int)tie_cnt[w] : 64;
        unsigned ku = (prefix & 0x80000000u) ? (prefix ^ 0x80000000u) : ~prefix;
        float kval = __uint_as_float(ku);
        for (int e = 0; e < needed; e++) {
            int bi = -1; unsigned bidx = 0xFFFFFFFFu;
            for (int t = 0; t < cnt; t++)
                if (tie_idx[w][t] < bidx) { bidx = tie_idx[w][t]; bi = t; }
            if (bi >= 0) { orow[bidx] = kval; tie_idx[w][bi] = 0xFFFFFFFFu; }
        }
    }
}

// ---------------------------------------------------------------------------
extern "C" void kernel_launch(void* const* d_in, const int* in_sizes, int n_in,
                              void* d_out, int out_size)
{
    const float* x     = (const float*)d_in[0];
    const float* Wq    = (const float*)d_in[1];
    const float* bq    = (const float*)d_in[2];
    const float* Wk    = (const float*)d_in[3];
    const float* bk    = (const float*)d_in[4];
    const float* mlp_w = (const float*)d_in[5];
    const float* mlp_b = (const float*)d_in[6];

    float* out = (float*)d_out;

    qk_kernel<<<1536, 128>>>(x, Wq, bq, Wk, bk);   // also resets g_ctr

    cudaFuncSetAttribute(score_kernel,
                         cudaFuncAttributeMaxDynamicSharedMemorySize, SMEMSZ);
    score_kernel<<<444, 256, SMEMSZ>>>(mlp_w, mlp_b, out);

    topk_kernel<<<BATCH * NODES / 8, 256>>>(out);
}

// round 10
// speedup vs baseline: 1.2541x; 1.2541x over previous
#include <cuda_runtime.h>
#include <cuda_fp16.h>
#include <cstdint>
#include <cstddef>

#define BATCH   8
#define NODES   2048
#define IN_DIM  64
#define HEADS   4
#define UDIM    1024
#define NNB     32

// fp16 hi/lo split operands
__device__ __half g_Xs[BATCH * NODES * 128];   // x rows: [hi 64 | lo 64]
__device__ __half g_Ws[2 * 128 * 128];         // W rows (Wq,Wk): [hi 64 | lo 64]
__device__ __half g_Qh[BATCH * NODES * 256];   // q rows (pre-scaled): per head [hi32|lo32]
__device__ __half g_Kh[BATCH * UDIM  * 256];
__device__ float  g_S [BATCH * NODES * UDIM];  // scores

#define CP16(dst, src) asm volatile("cp.async.cg.shared.global [%0], [%1], 16;" :: "r"(dst), "l"(src))
#define CPCOMMIT()     asm volatile("cp.async.commit_group;" ::: "memory")
#define CPWAIT0()      asm volatile("cp.async.wait_group 0;" ::: "memory")

__device__ __forceinline__ uint32_t smem_u32(const void* p) {
    uint32_t a;
    asm("{ .reg .u64 t; cvta.to.shared.u64 t, %1; cvt.u32.u64 %0, t; }" : "=r"(a) : "l"(p));
    return a;
}
__device__ __forceinline__ void mma_f16(float* c, const uint32_t* a, const uint32_t* b) {
    asm volatile("mma.sync.aligned.m16n8k16.row.col.f32.f16.f16.f32 "
        "{%0,%1,%2,%3}, {%4,%5,%6,%7}, {%8,%9}, {%0,%1,%2,%3};"
        : "+f"(c[0]), "+f"(c[1]), "+f"(c[2]), "+f"(c[3])
        : "r"(a[0]), "r"(a[1]), "r"(a[2]), "r"(a[3]), "r"(b[0]), "r"(b[1]));
}
__device__ __forceinline__ void ldsm_x4(uint32_t* r, uint32_t addr) {
    asm volatile("ldmatrix.sync.aligned.m8n8.x4.shared.b16 {%0,%1,%2,%3}, [%4];"
        : "=r"(r[0]), "=r"(r[1]), "=r"(r[2]), "=r"(r[3]) : "r"(addr));
}

// ---------------------------------------------------------------------------
// Kernel 0: split x and W into fp16 hi/lo.
//   Blocks [0,1024): x (4 floats/thread). Blocks [1024,1032): Wq|Wk.
// ---------------------------------------------------------------------------
__global__ void __launch_bounds__(256) prep_kernel(
    const float* __restrict__ x,
    const float* __restrict__ Wq, const float* __restrict__ Wk)
{
    if (blockIdx.x < 1024) {
        const int gid = (blockIdx.x * 256 + threadIdx.x) * 4;
        float4 v = *(const float4*)(x + gid);
        const int row = gid >> 6, k = gid & 63;
        __half* dst = g_Xs + (size_t)row * 128 + k;
        float f[4] = {v.x, v.y, v.z, v.w};
        __half h[4], l[4];
#pragma unroll
        for (int i = 0; i < 4; i++) {
            h[i] = __float2half_rn(f[i]);
            l[i] = __float2half_rn(f[i] - __half2float(h[i]));
        }
#pragma unroll
        for (int i = 0; i < 4; i++) { dst[i] = h[i]; dst[64 + i] = l[i]; }
    } else {
        const int g0 = (blockIdx.x - 1024) * 2048 + threadIdx.x * 8;
#pragma unroll
        for (int i = 0; i < 8; i++) {
            const int g = g0 + i;
            const float v = (g < 8192) ? Wq[g] : Wk[g - 8192];
            const int which = g >> 13, c = (g & 8191) >> 6, k = g & 63;
            __half h = __float2half_rn(v);
            __half l = __float2half_rn(v - __half2float(h));
            __half* dst = g_Ws + (size_t)which * 16384 + c * 128 + k;
            dst[0] = h; dst[64] = l;
        }
    }
}

// ---------------------------------------------------------------------------
// Kernel 1: QK projection via HMMA (3-combo split), 128n x 128c x k64 tiles.
//   Blocks [0,128): Q (8b x 16 tiles). Blocks [128,192): K (8b x 8 tiles).
// Epilogue: (acc + bias)*scale -> hi/lo re-split -> g_Qh/g_Kh head layout.
// ---------------------------------------------------------------------------
#define XROW    272                    // 256B row + 16B pad
#define QG_SMX  0                      // 128*272 = 34816
#define QG_SMW  34816                  // 34816
#define QG_SB   69632                  // 128 floats (bias*scale)
#define QG_SMEM 70144

__global__ void __launch_bounds__(256) qkgemm_kernel(
    const float* __restrict__ bq, const float* __restrict__ bk)
{
    extern __shared__ __align__(16) char sm[];
    const uint32_t smb = smem_u32(sm);
    const int tid = threadIdx.x, lane = tid & 31, wid = tid >> 5;

    const bool isQ = (blockIdx.x < 128);
    int b, n0; const float* bias; float scale;
    if (isQ) { b = blockIdx.x >> 4;            n0 = (blockIdx.x & 15) << 7; bias = bq; scale = 0.17677669529663687f; }
    else     { int id = blockIdx.x - 128; b = id >> 3; n0 = (id & 7) << 7;  bias = bk; scale = 1.0f; }

    // stage X tile (rows shared by Q and K paths) and W
    {
        const char* xsrc = (const char*)(g_Xs + ((size_t)(b * NODES + n0)) * 128);
        const char* wsrc = (const char*)(g_Ws + (isQ ? 0 : 16384));
#pragma unroll
        for (int it = 0; it < 8; it++) {
            int idx = it * 256 + tid;          // 2048 x 16B
            int row = idx >> 4, j = idx & 15;
            CP16(smb + QG_SMX + row * XROW + j * 16, xsrc + row * 256 + j * 16);
            CP16(smb + QG_SMW + row * XROW + j * 16, wsrc + row * 256 + j * 16);
        }
    }
    if (tid < 128) ((float*)(sm + QG_SB))[tid] = bias[tid] * scale;
    CPCOMMIT();
    CPWAIT0();
    __syncthreads();

    const int r0 = wid << 4;                   // warp rows (16)
    // A fragments: [kstep][part][4]
    uint32_t aF[4][2][4];
    {
        const uint32_t qb = smb + QG_SMX + (r0 + (lane & 15)) * XROW + ((lane >> 4) << 4);
#pragma unroll
        for (int s = 0; s < 4; s++)
#pragma unroll
            for (int p = 0; p < 2; p++)
                ldsm_x4(aF[s][p], qb + p * 128 + s * 32);
    }

    float acc[16][4];
#pragma unroll
    for (int j = 0; j < 16; j++)
#pragma unroll
        for (int q = 0; q < 4; q++) acc[j][q] = 0.f;

#pragma unroll
    for (int j = 0; j < 16; j++) {
        const uint32_t kb = smb + QG_SMW + (j * 8 + (lane & 7)) * XROW + ((lane >> 3) << 4);
        uint32_t bh0[4], bh1[4], bl0[4], bl1[4];
        ldsm_x4(bh0, kb);        // hi k0-31
        ldsm_x4(bh1, kb + 64);   // hi k32-63
        ldsm_x4(bl0, kb + 128);  // lo k0-31
        ldsm_x4(bl1, kb + 192);  // lo k32-63
#pragma unroll
        for (int s = 0; s < 4; s++) {
            const uint32_t* bh = (s < 2) ? (bh0 + 2 * s) : (bh1 + 2 * (s - 2));
            const uint32_t* bl = (s < 2) ? (bl0 + 2 * s) : (bl1 + 2 * (s - 2));
            mma_f16(acc[j], aF[s][0], bh);   // xh*wh
            mma_f16(acc[j], aF[s][0], bl);   // xh*wl
            mma_f16(acc[j], aF[s][1], bh);   // xl*wh
        }
    }

    // epilogue: bias+scale, re-split hi/lo, store head layout
    const float* sb = (const float*)(sm + QG_SB);
    const int ra = n0 + r0 + (lane >> 2);
    __half* gout = isQ ? g_Qh : g_Kh;
    const size_t base = ((size_t)(b * (isQ ? NODES : UDIM) + ra)) * 256;
#pragma unroll
    for (int j = 0; j < 16; j++) {
        const int c0 = j * 8 + (lane & 3) * 2;
        const float b0 = sb[c0], b1 = sb[c0 + 1];
        const int o = ((c0 >> 5) << 6) + (c0 & 31);
#pragma unroll
        for (int rr = 0; rr < 2; rr++) {
            float v0 = fmaf(acc[j][2 * rr],     scale, b0);
            float v1 = fmaf(acc[j][2 * rr + 1], scale, b1);
            __half h0 = __float2half_rn(v0), h1 = __float2half_rn(v1);
            __half l0 = __float2half_rn(v0 - __half2float(h0));
            __half l1 = __float2half_rn(v1 - __half2float(h1));
            uint32_t hp = ((uint32_t)__half_as_ushort(h1) << 16) | __half_as_ushort(h0);
            uint32_t lp = ((uint32_t)__half_as_ushort(l1) << 16) | __half_as_ushort(l0);
            __half* dst = gout + base + (size_t)rr * 8 * 256 + o;
            *(uint32_t*)dst        = hp;
            *(uint32_t*)(dst + 32) = lp;
        }
    }
}

// ---------------------------------------------------------------------------
// Kernel 2: score kernel (R3 structure, 3-combo, ldmatrix-B, zero interleave).
// 128 blocks x 256 thr; block = (b, 128 n-rows) x full 1024 u.
// 32 chunks of 32u, cp.async double-buffered; warp = 16n, 4 utiles x 8u.
// ---------------------------------------------------------------------------
#define SKROW   528
#define SMQ     0                      // 128*528 = 67584
#define SMK     67584                  // 2*32*528 = 33792
#define KBUF    (32 * SKROW)
#define SC_SMEM 101376

__device__ __forceinline__ void fillK_async(uint32_t smb, int b, int ustart, int buf, int tid) {
    const char* src = (const char*)(g_Kh + ((size_t)(b * UDIM + ustart)) * 256);
    const uint32_t dst = smb + SMK + buf * KBUF;
#pragma unroll
    for (int it = 0; it < 4; it++) {
        int idx = it * 256 + tid;            // 32 rows x 32 x 16B
        int row = idx >> 5, j = idx & 31;
        CP16(dst + row * SKROW + j * 16, src + row * 512 + j * 16);
    }
}

__global__ void __launch_bounds__(256) score_kernel(
    const float* __restrict__ mlp_w, const float* __restrict__ mlp_b,
    float* __restrict__ out)
{
    extern __shared__ __align__(16) char sm[];
    const uint32_t smb = smem_u32(sm);
    const int tid = threadIdx.x, lane = tid & 31, wid = tid >> 5;
    const int wr0 = wid << 4;                 // warp n-offset (16 rows)
    const int b  = blockIdx.x >> 4;
    const int n0 = (blockIdx.x & 15) << 7;

    // stage Q tile (128 rows x 512B) + K chunk 0
    {
        const char* qsrc = (const char*)(g_Qh + ((size_t)(b * NODES + n0)) * 256);
#pragma unroll
        for (int it = 0; it < 16; it++) {
            int idx = it * 256 + tid;
            int row = idx >> 5, j = idx & 31;
            CP16(smb + SMQ + row * SKROW + j * 16, qsrc + row * 512 + j * 16);
        }
    }
    fillK_async(smb, b, 0, 0, tid);
    CPCOMMIT();

    float mm[4][4], mb_[4];
#pragma unroll
    for (int o = 0; o < 4; o++) {
        mb_[o] = mlp_b[o];
#pragma unroll
        for (int h = 0; h < 4; h++) mm[o][h] = mlp_w[o * 4 + h];
    }
    CPWAIT0();
    __syncthreads();

    // A fragments cached for all 32 chunks (R3-proven plain-LDS addressing)
    uint32_t aF[4][2][2][4];                  // [head][part][kstep][4]
    {
        const char* qb = sm + SMQ + (wr0 + (lane >> 2)) * SKROW;
#pragma unroll
        for (int h = 0; h < 4; h++)
#pragma unroll
            for (int p = 0; p < 2; p++)
#pragma unroll
                for (int s = 0; s < 2; s++) {
                    int off = (h * 64 + p * 32 + s * 16 + (lane & 3) * 2) * 2;
                    aF[h][p][s][0] = *(const uint32_t*)(qb + off);
                    aF[h][p][s][1] = *(const uint32_t*)(qb + off + 8 * SKROW);
                    aF[h][p][s][2] = *(const uint32_t*)(qb + off + 16);
                    aF[h][p][s][3] = *(const uint32_t*)(qb + off + 8 * SKROW + 16);
                }
    }

    for (int ck = 0; ck < 32; ck++) {
        const int buf = ck & 1;
        CPWAIT0();
        __syncthreads();
        if (ck + 1 < 32) { fillK_async(smb, b, (ck + 1) * 32, buf ^ 1, tid); CPCOMMIT(); }

        // zero-fill 4 of this block's 128 output rows (hidden under compute)
        {
            const int zr = ck * 4 + (tid >> 6);
            float4* zrow = (float4*)(out + ((size_t)(b * NODES + n0 + zr)) * NODES);
            const float4 z4 = make_float4(0.f, 0.f, 0.f, 0.f);
#pragma unroll
            for (int i = 0; i < 8; i++) zrow[i * 64 + (tid & 63)] = z4;
        }

        float acc[4][4][4];                   // [utile][head][frag]
#pragma unroll
        for (int ut = 0; ut < 4; ut++)
#pragma unroll
            for (int h = 0; h < 4; h++)
#pragma unroll
                for (int q = 0; q < 4; q++) acc[ut][h][q] = 0.f;

#pragma unroll
        for (int ut = 0; ut < 4; ut++) {
            const uint32_t kb = smb + SMK + buf * KBUF +
                                (ut * 8 + (lane & 7)) * SKROW + ((lane >> 3) << 4);
#pragma unroll
            for (int h = 0; h < 4; h++) {
                uint32_t bh[4], bl[4];
                ldsm_x4(bh, kb + h * 128);        // hi k0-31
                ldsm_x4(bl, kb + h * 128 + 64);   // lo k0-31
#pragma unroll
                for (int s = 0; s < 2; s++) {
                    mma_f16(acc[ut][h], aF[h][0][s], bh + 2 * s);   // hh
                    mma_f16(acc[ut][h], aF[h][0][s], bl + 2 * s);   // hl
                    mma_f16(acc[ut][h], aF[h][1][s], bh + 2 * s);   // lh
                }
            }
        }

        // epilogue: head mix + relu + residual -> g_S
        const int u0 = ck * 32;
#pragma unroll
        for (int ut = 0; ut < 4; ut++) {
            float s_[4];
#pragma unroll
            for (int q = 0; q < 4; q++) {
                float a0 = acc[ut][0][q], a1 = acc[ut][1][q];
                float a2 = acc[ut][2][q], a3 = acc[ut][3][q];
                float s = a0 + a1 + a2 + a3;
#pragma unroll
                for (int o = 0; o < 4; o++) {
                    float z = fmaf(mm[o][0], a0, fmaf(mm[o][1], a1,
                              fmaf(mm[o][2], a2, fmaf(mm[o][3], a3, mb_[o]))));
                    s += fmaxf(z, 0.f);
                }
                s_[q] = s;
            }
            float* sg = g_S + ((size_t)(b * NODES + n0 + wr0 + (lane >> 2))) * UDIM
                        + u0 + ut * 8 + (lane & 3) * 2;
            *(float2*)sg              = make_float2(s_[0], s_[1]);
            *(float2*)(sg + 8 * UDIM) = make_float2(s_[2], s_[3]);
        }
    }
}

// ---------------------------------------------------------------------------
// Kernel 3: top-32 per row via radix select (R9-proven, select+scatter only).
// ---------------------------------------------------------------------------
__global__ void __launch_bounds__(256) topk_kernel(float* __restrict__ out)
{
    const int w = threadIdx.x >> 5, lane = threadIdx.x & 31;
    const int row = blockIdx.x * 8 + w;
    __shared__ unsigned hist[8][256];
    __shared__ unsigned tie_idx[8][64];
    __shared__ unsigned found[8][2];
    __shared__ unsigned tie_cnt[8];

    const float* srow = g_S + (size_t)row * UDIM;
    float    vals[32];
    unsigned keys[32];
#pragma unroll
    for (int j = 0; j < 32; j++) {
        float v = srow[j * 32 + lane];
        vals[j] = v;
        unsigned u = __float_as_uint(v);
        keys[j] = u ^ (((unsigned)((int)u >> 31)) | 0x80000000u);
    }

    unsigned prefix = 0;
    int needed = NNB;
    for (int shift = 24; shift >= 0; shift -= 8) {
        for (int t = lane; t < 256; t += 32) hist[w][t] = 0;
        __syncwarp();
        const unsigned hm = (shift == 24) ? 0u : (0xFFFFFFFFu << (shift + 8));
#pragma unroll
        for (int j = 0; j < 32; j++)
            if (((keys[j] ^ prefix) & hm) == 0)
                atomicAdd(&hist[w][(keys[j] >> shift) & 255], 1u);
        __syncwarp();
        unsigned s = 0;
#pragma unroll
        for (int t = 0; t < 8; t++) s += hist[w][lane * 8 + t];
        unsigned rs = s;
#pragma unroll
        for (int off = 1; off < 32; off <<= 1) {
            unsigned v = __shfl_down_sync(0xffffffffu, rs, off);
            if (lane + off < 32) rs += v;
        }
        unsigned acc = rs - s;
        for (int t = 7; t >= 0; t--) {
            unsigned c = hist[w][lane * 8 + t];
            if ((int)acc < needed && needed <= (int)(acc + c)) {
                found[w][0] = (unsigned)(lane * 8 + t);
                found[w][1] = acc;
            }
            acc += c;
        }
        __syncwarp();
        prefix |= found[w][0] << shift;
        needed -= (int)found[w][1];
        __syncwarp();
    }

    const int b = row >> 11, n = row & 2047;
    float* orow = out + ((size_t)b * NODES + n) * (size_t)NODES;
    if (lane == 0) tie_cnt[w] = 0;
    __syncwarp();
#pragma unroll
    for (int j = 0; j < 32; j++) {
        if (keys[j] > prefix) orow[j * 32 + lane] = vals[j];
        else if (keys[j] == prefix) {
            unsigned p = atomicAdd(&tie_cnt[w], 1u);
            if (p < 64) tie_idx[w][p] = (unsigned)(j * 32 + lane);
        }
    }
    __syncwarp();
    if (lane == 0) {
        int cnt = tie_cnt[w] < 64 ? (int)tie_cnt[w] : 64;
        unsigned ku = (prefix & 0x80000000u) ? (prefix ^ 0x80000000u) : ~prefix;
        float kval = __uint_as_float(ku);
        for (int e = 0; e < needed; e++) {
            int bi = -1; unsigned bidx = 0xFFFFFFFFu;
            for (int t = 0; t < cnt; t++)
                if (tie_idx[w][t] < bidx) { bidx = tie_idx[w][t]; bi = t; }
            if (bi >= 0) { orow[bidx] = kval; tie_idx[w][bi] = 0xFFFFFFFFu; }
        }
    }
}

// ---------------------------------------------------------------------------
extern "C" void kernel_launch(void* const* d_in, const int* in_sizes, int n_in,
                              void* d_out, int out_size)
{
    const float* x     = (const float*)d_in[0];
    const float* Wq    = (const float*)d_in[1];
    const float* bq    = (const float*)d_in[2];
    const float* Wk    = (const float*)d_in[3];
    const float* bk    = (const float*)d_in[4];
    const float* mlp_w = (const float*)d_in[5];
    const float* mlp_b = (const float*)d_in[6];

    float* out = (float*)d_out;

    prep_kernel<<<1032, 256>>>(x, Wq, Wk);

    cudaFuncSetAttribute(qkgemm_kernel,
                         cudaFuncAttributeMaxDynamicSharedMemorySize, QG_SMEM);
    qkgemm_kernel<<<192, 256, QG_SMEM>>>(bq, bk);

    cudaFuncSetAttribute(score_kernel,
                         cudaFuncAttributeMaxDynamicSharedMemorySize, SC_SMEM);
    score_kernel<<<128, 256, SC_SMEM>>>(mlp_w, mlp_b, out);

    topk_kernel<<<BATCH * NODES / 8, 256>>>(out);
}

// round 11
// speedup vs baseline: 1.4323x; 1.1421x over previous
#include <cuda_runtime.h>
#include <cuda_fp16.h>
#include <cstdint>
#include <cstddef>

#define BATCH   8
#define NODES   2048
#define IN_DIM  64
#define HEADS   4
#define UDIM    1024
#define NNB     32

// fp16 hi/lo split operands
__device__ __half g_Xs[BATCH * NODES * 128];   // x rows: [hi 64 | lo 64]
__device__ __half g_Ws[2 * 128 * 128];         // W rows (Wq,Wk): [hi 64 | lo 64]
__device__ __half g_Qh[BATCH * NODES * 256];   // q rows (pre-scaled): per head [hi32|lo32]
__device__ __half g_Kh[BATCH * UDIM  * 256];
__device__ float  g_S [BATCH * NODES * UDIM];  // scores

#define CP16(dst, src) asm volatile("cp.async.cg.shared.global [%0], [%1], 16;" :: "r"(dst), "l"(src))
#define CPCOMMIT()     asm volatile("cp.async.commit_group;" ::: "memory")
#define CPWAIT0()      asm volatile("cp.async.wait_group 0;" ::: "memory")

__device__ __forceinline__ uint32_t smem_u32(const void* p) {
    uint32_t a;
    asm("{ .reg .u64 t; cvta.to.shared.u64 t, %1; cvt.u32.u64 %0, t; }" : "=r"(a) : "l"(p));
    return a;
}
__device__ __forceinline__ void mma_f16(float* c, const uint32_t* a, const uint32_t* b) {
    asm volatile("mma.sync.aligned.m16n8k16.row.col.f32.f16.f16.f32 "
        "{%0,%1,%2,%3}, {%4,%5,%6,%7}, {%8,%9}, {%0,%1,%2,%3};"
        : "+f"(c[0]), "+f"(c[1]), "+f"(c[2]), "+f"(c[3])
        : "r"(a[0]), "r"(a[1]), "r"(a[2]), "r"(a[3]), "r"(b[0]), "r"(b[1]));
}
__device__ __forceinline__ void ldsm_x4(uint32_t* r, uint32_t addr) {
    asm volatile("ldmatrix.sync.aligned.m8n8.x4.shared.b16 {%0,%1,%2,%3}, [%4];"
        : "=r"(r[0]), "=r"(r[1]), "=r"(r[2]), "=r"(r[3]) : "r"(addr));
}

// ---------------------------------------------------------------------------
// Kernel 0: split x and W into fp16 hi/lo.
// ---------------------------------------------------------------------------
__global__ void __launch_bounds__(256) prep_kernel(
    const float* __restrict__ x,
    const float* __restrict__ Wq, const float* __restrict__ Wk)
{
    if (blockIdx.x < 1024) {
        const int gid = (blockIdx.x * 256 + threadIdx.x) * 4;
        float4 v = *(const float4*)(x + gid);
        const int row = gid >> 6, k = gid & 63;
        __half* dst = g_Xs + (size_t)row * 128 + k;
        float f[4] = {v.x, v.y, v.z, v.w};
        __half h[4], l[4];
#pragma unroll
        for (int i = 0; i < 4; i++) {
            h[i] = __float2half_rn(f[i]);
            l[i] = __float2half_rn(f[i] - __half2float(h[i]));
        }
#pragma unroll
        for (int i = 0; i < 4; i++) { dst[i] = h[i]; dst[64 + i] = l[i]; }
    } else {
        const int g0 = (blockIdx.x - 1024) * 2048 + threadIdx.x * 8;
#pragma unroll
        for (int i = 0; i < 8; i++) {
            const int g = g0 + i;
            const float v = (g < 8192) ? Wq[g] : Wk[g - 8192];
            const int which = g >> 13, c = (g & 8191) >> 6, k = g & 63;
            __half h = __float2half_rn(v);
            __half l = __float2half_rn(v - __half2float(h));
            __half* dst = g_Ws + (size_t)which * 16384 + c * 128 + k;
            dst[0] = h; dst[64] = l;
        }
    }
}

// ---------------------------------------------------------------------------
// Kernel 1: QK projection via HMMA (R10-proven).
// ---------------------------------------------------------------------------
#define XROW    272
#define QG_SMX  0
#define QG_SMW  34816
#define QG_SB   69632
#define QG_SMEM 70144

__global__ void __launch_bounds__(256) qkgemm_kernel(
    const float* __restrict__ bq, const float* __restrict__ bk)
{
    extern __shared__ __align__(16) char sm[];
    const uint32_t smb = smem_u32(sm);
    const int tid = threadIdx.x, lane = tid & 31, wid = tid >> 5;

    const bool isQ = (blockIdx.x < 128);
    int b, n0; const float* bias; float scale;
    if (isQ) { b = blockIdx.x >> 4;            n0 = (blockIdx.x & 15) << 7; bias = bq; scale = 0.17677669529663687f; }
    else     { int id = blockIdx.x - 128; b = id >> 3; n0 = (id & 7) << 7;  bias = bk; scale = 1.0f; }

    {
        const char* xsrc = (const char*)(g_Xs + ((size_t)(b * NODES + n0)) * 128);
        const char* wsrc = (const char*)(g_Ws + (isQ ? 0 : 16384));
#pragma unroll
        for (int it = 0; it < 8; it++) {
            int idx = it * 256 + tid;
            int row = idx >> 4, j = idx & 15;
            CP16(smb + QG_SMX + row * XROW + j * 16, xsrc + row * 256 + j * 16);
            CP16(smb + QG_SMW + row * XROW + j * 16, wsrc + row * 256 + j * 16);
        }
    }
    if (tid < 128) ((float*)(sm + QG_SB))[tid] = bias[tid] * scale;
    CPCOMMIT();
    CPWAIT0();
    __syncthreads();

    const int r0 = wid << 4;
    uint32_t aF[4][2][4];
    {
        const uint32_t qb = smb + QG_SMX + (r0 + (lane & 15)) * XROW + ((lane >> 4) << 4);
#pragma unroll
        for (int s = 0; s < 4; s++)
#pragma unroll
            for (int p = 0; p < 2; p++)
                ldsm_x4(aF[s][p], qb + p * 128 + s * 32);
    }

    float acc[16][4];
#pragma unroll
    for (int j = 0; j < 16; j++)
#pragma unroll
        for (int q = 0; q < 4; q++) acc[j][q] = 0.f;

#pragma unroll
    for (int j = 0; j < 16; j++) {
        const uint32_t kb = smb + QG_SMW + (j * 8 + (lane & 7)) * XROW + ((lane >> 3) << 4);
        uint32_t bh0[4], bh1[4], bl0[4], bl1[4];
        ldsm_x4(bh0, kb);
        ldsm_x4(bh1, kb + 64);
        ldsm_x4(bl0, kb + 128);
        ldsm_x4(bl1, kb + 192);
#pragma unroll
        for (int s = 0; s < 4; s++) {
            const uint32_t* bh = (s < 2) ? (bh0 + 2 * s) : (bh1 + 2 * (s - 2));
            const uint32_t* bl = (s < 2) ? (bl0 + 2 * s) : (bl1 + 2 * (s - 2));
            mma_f16(acc[j], aF[s][0], bh);
            mma_f16(acc[j], aF[s][0], bl);
            mma_f16(acc[j], aF[s][1], bh);
        }
    }

    const float* sb = (const float*)(sm + QG_SB);
    const int ra = n0 + r0 + (lane >> 2);
    __half* gout = isQ ? g_Qh : g_Kh;
    const size_t base = ((size_t)(b * (isQ ? NODES : UDIM) + ra)) * 256;
#pragma unroll
    for (int j = 0; j < 16; j++) {
        const int c0 = j * 8 + (lane & 3) * 2;
        const float b0 = sb[c0], b1 = sb[c0 + 1];
        const int o = ((c0 >> 5) << 6) + (c0 & 31);
#pragma unroll
        for (int rr = 0; rr < 2; rr++) {
            float v0 = fmaf(acc[j][2 * rr],     scale, b0);
            float v1 = fmaf(acc[j][2 * rr + 1], scale, b1);
            __half h0 = __float2half_rn(v0), h1 = __float2half_rn(v1);
            __half l0 = __float2half_rn(v0 - __half2float(h0));
            __half l1 = __float2half_rn(v1 - __half2float(h1));
            uint32_t hp = ((uint32_t)__half_as_ushort(h1) << 16) | __half_as_ushort(h0);
            uint32_t lp = ((uint32_t)__half_as_ushort(l1) << 16) | __half_as_ushort(l0);
            __half* dst = gout + base + (size_t)rr * 8 * 256 + o;
            *(uint32_t*)dst        = hp;
            *(uint32_t*)(dst + 32) = lp;
        }
    }
}

// ---------------------------------------------------------------------------
// Kernel 2: score kernel, 256 blocks x 64 n-rows, 2 blocks/SM (single wave).
// 8 warps = 4n x 2u; warp tile 16n x 16u per 32u chunk; aF register-cached.
// Zero-fill (streaming stores) interleaved: 2 rows/chunk.
// ---------------------------------------------------------------------------
#define SKROW   528
#define SMQ     0                      // 64*528 = 33792
#define SMK     33792                  // 2*32*528 = 33792
#define KBUF    (32 * SKROW)
#define SC_SMEM 67584

__device__ __forceinline__ void fillK_async(uint32_t smb, int b, int ustart, int buf, int tid) {
    const char* src = (const char*)(g_Kh + ((size_t)(b * UDIM + ustart)) * 256);
    const uint32_t dst = smb + SMK + buf * KBUF;
#pragma unroll
    for (int it = 0; it < 4; it++) {
        int idx = it * 256 + tid;
        int row = idx >> 5, j = idx & 31;
        CP16(dst + row * SKROW + j * 16, src + row * 512 + j * 16);
    }
}

__global__ void __launch_bounds__(256, 2) score_kernel(
    const float* __restrict__ mlp_w, const float* __restrict__ mlp_b,
    float* __restrict__ out)
{
    extern __shared__ __align__(16) char sm[];
    const uint32_t smb = smem_u32(sm);
    const int tid = threadIdx.x, lane = tid & 31, wid = tid >> 5;
    const int wr0 = (wid & 3) << 4;           // warp n-offset (0..48)
    const int uw0 = (wid >> 2) << 4;          // warp u-offset in chunk (0/16)
    const int b  = blockIdx.x >> 5;
    const int n0 = (blockIdx.x & 31) << 6;

    // stage Q tile (64 rows x 512B) + K chunk 0
    {
        const char* qsrc = (const char*)(g_Qh + ((size_t)(b * NODES + n0)) * 256);
#pragma unroll
        for (int it = 0; it < 8; it++) {
            int idx = it * 256 + tid;
            int row = idx >> 5, j = idx & 31;
            CP16(smb + SMQ + row * SKROW + j * 16, qsrc + row * 512 + j * 16);
        }
    }
    fillK_async(smb, b, 0, 0, tid);
    CPCOMMIT();

    float mm[4][4], mb_[4];
#pragma unroll
    for (int o = 0; o < 4; o++) {
        mb_[o] = mlp_b[o];
#pragma unroll
        for (int h = 0; h < 4; h++) mm[o][h] = mlp_w[o * 4 + h];
    }
    CPWAIT0();
    __syncthreads();

    // A fragments cached for all 32 chunks
    uint32_t aF[4][2][2][4];                  // [head][part][kstep][4]
    {
        const char* qb = sm + SMQ + (wr0 + (lane >> 2)) * SKROW;
#pragma unroll
        for (int h = 0; h < 4; h++)
#pragma unroll
            for (int p = 0; p < 2; p++)
#pragma unroll
                for (int s = 0; s < 2; s++) {
                    int off = (h * 64 + p * 32 + s * 16 + (lane & 3) * 2) * 2;
                    aF[h][p][s][0] = *(const uint32_t*)(qb + off);
                    aF[h][p][s][1] = *(const uint32_t*)(qb + off + 8 * SKROW);
                    aF[h][p][s][2] = *(const uint32_t*)(qb + off + 16);
                    aF[h][p][s][3] = *(const uint32_t*)(qb + off + 8 * SKROW + 16);
                }
    }

    for (int ck = 0; ck < 32; ck++) {
        const int buf = ck & 1;
        CPWAIT0();
        __syncthreads();
        if (ck + 1 < 32) { fillK_async(smb, b, (ck + 1) * 32, buf ^ 1, tid); CPCOMMIT(); }

        // zero-fill 2 of this block's 64 output rows (streaming: don't pollute L2)
        {
            const int zr = ck * 2 + (tid >> 7);
            float4* zrow = (float4*)(out + ((size_t)(b * NODES + n0 + zr)) * NODES);
            const float4 z4 = make_float4(0.f, 0.f, 0.f, 0.f);
#pragma unroll
            for (int i = 0; i < 4; i++) __stcs(zrow + i * 128 + (tid & 127), z4);
        }

        float acc[2][4][4];                   // [utile][head][frag]
#pragma unroll
        for (int ut = 0; ut < 2; ut++)
#pragma unroll
            for (int h = 0; h < 4; h++)
#pragma unroll
                for (int q = 0; q < 4; q++) acc[ut][h][q] = 0.f;

#pragma unroll
        for (int ut = 0; ut < 2; ut++) {
            const uint32_t kb = smb + SMK + buf * KBUF +
                                (uw0 + ut * 8 + (lane & 7)) * SKROW + ((lane >> 3) << 4);
#pragma unroll
            for (int h = 0; h < 4; h++) {
                uint32_t bh[4], bl[4];
                ldsm_x4(bh, kb + h * 128);
                ldsm_x4(bl, kb + h * 128 + 64);
#pragma unroll
                for (int s = 0; s < 2; s++) {
                    mma_f16(acc[ut][h], aF[h][0][s], bh + 2 * s);   // hh
                    mma_f16(acc[ut][h], aF[h][0][s], bl + 2 * s);   // hl
                    mma_f16(acc[ut][h], aF[h][1][s], bh + 2 * s);   // lh
                }
            }
        }

        const int u0 = ck * 32;
#pragma unroll
        for (int ut = 0; ut < 2; ut++) {
            float s_[4];
#pragma unroll
            for (int q = 0; q < 4; q++) {
                float a0 = acc[ut][0][q], a1 = acc[ut][1][q];
                float a2 = acc[ut][2][q], a3 = acc[ut][3][q];
                float s = a0 + a1 + a2 + a3;
#pragma unroll
                for (int o = 0; o < 4; o++) {
                    float z = fmaf(mm[o][0], a0, fmaf(mm[o][1], a1,
                              fmaf(mm[o][2], a2, fmaf(mm[o][3], a3, mb_[o]))));
                    s += fmaxf(z, 0.f);
                }
                s_[q] = s;
            }
            float* sg = g_S + ((size_t)(b * NODES + n0 + wr0 + (lane >> 2))) * UDIM
                        + u0 + uw0 + ut * 8 + (lane & 3) * 2;
            *(float2*)sg              = make_float2(s_[0], s_[1]);
            *(float2*)(sg + 8 * UDIM) = make_float2(s_[2], s_[3]);
        }
    }
}

// ---------------------------------------------------------------------------
// Kernel 3: top-32 per row, radix select. vals recomputed from keys (bijective)
// -> ~64 regs -> 3 blocks/SM.
// ---------------------------------------------------------------------------
__device__ __forceinline__ float key2val(unsigned k) {
    unsigned u = (k & 0x80000000u) ? (k ^ 0x80000000u) : ~k;
    return __uint_as_float(u);
}

__global__ void __launch_bounds__(256, 3) topk_kernel(float* __restrict__ out)
{
    const int w = threadIdx.x >> 5, lane = threadIdx.x & 31;
    const int row = blockIdx.x * 8 + w;
    __shared__ unsigned hist[8][256];
    __shared__ unsigned tie_idx[8][64];
    __shared__ unsigned found[8][2];
    __shared__ unsigned tie_cnt[8];

    const float* srow = g_S + (size_t)row * UDIM;
    unsigned keys[32];
#pragma unroll
    for (int j = 0; j < 32; j++) {
        unsigned u = __float_as_uint(srow[j * 32 + lane]);
        keys[j] = u ^ (((unsigned)((int)u >> 31)) | 0x80000000u);
    }

    unsigned prefix = 0;
    int needed = NNB;
    for (int shift = 24; shift >= 0; shift -= 8) {
        for (int t = lane; t < 256; t += 32) hist[w][t] = 0;
        __syncwarp();
        const unsigned hm = (shift == 24) ? 0u : (0xFFFFFFFFu << (shift + 8));
#pragma unroll
        for (int j = 0; j < 32; j++)
            if (((keys[j] ^ prefix) & hm) == 0)
                atomicAdd(&hist[w][(keys[j] >> shift) & 255], 1u);
        __syncwarp();
        unsigned s = 0;
#pragma unroll
        for (int t = 0; t < 8; t++) s += hist[w][lane * 8 + t];
        unsigned rs = s;
#pragma unroll
        for (int off = 1; off < 32; off <<= 1) {
            unsigned v = __shfl_down_sync(0xffffffffu, rs, off);
            if (lane + off < 32) rs += v;
        }
        unsigned acc = rs - s;
        for (int t = 7; t >= 0; t--) {
            unsigned c = hist[w][lane * 8 + t];
            if ((int)acc < needed && needed <= (int)(acc + c)) {
                found[w][0] = (unsigned)(lane * 8 + t);
                found[w][1] = acc;
            }
            acc += c;
        }
        __syncwarp();
        prefix |= found[w][0] << shift;
        needed -= (int)found[w][1];
        __syncwarp();
    }

    const int b = row >> 11, n = row & 2047;
    float* orow = out + ((size_t)b * NODES + n) * (size_t)NODES;
    if (lane == 0) tie_cnt[w] = 0;
    __syncwarp();
#pragma unroll
    for (int j = 0; j < 32; j++) {
        if (keys[j] > prefix) orow[j * 32 + lane] = key2val(keys[j]);
        else if (keys[j] == prefix) {
            unsigned p = atomicAdd(&tie_cnt[w], 1u);
            if (p < 64) tie_idx[w][p] = (unsigned)(j * 32 + lane);
        }
    }
    __syncwarp();
    if (lane == 0) {
        int cnt = tie_cnt[w] < 64 ? (int)tie_cnt[w] : 64;
        float kval = key2val(prefix);
        for (int e = 0; e < needed; e++) {
            int bi = -1; unsigned bidx = 0xFFFFFFFFu;
            for (int t = 0; t < cnt; t++)
                if (tie_idx[w][t] < bidx) { bidx = tie_idx[w][t]; bi = t; }
            if (bi >= 0) { orow[bidx] = kval; tie_idx[w][bi] = 0xFFFFFFFFu; }
        }
    }
}

// ---------------------------------------------------------------------------
extern "C" void kernel_launch(void* const* d_in, const int* in_sizes, int n_in,
                              void* d_out, int out_size)
{
    const float* x     = (const float*)d_in[0];
    const float* Wq    = (const float*)d_in[1];
    const float* bq    = (const float*)d_in[2];
    const float* Wk    = (const float*)d_in[3];
    const float* bk    = (const float*)d_in[4];
    const float* mlp_w = (const float*)d_in[5];
    const float* mlp_b = (const float*)d_in[6];

    float* out = (float*)d_out;

    prep_kernel<<<1032, 256>>>(x, Wq, Wk);

    cudaFuncSetAttribute(qkgemm_kernel,
                         cudaFuncAttributeMaxDynamicSharedMemorySize, QG_SMEM);
    qkgemm_kernel<<<192, 256, QG_SMEM>>>(bq, bk);

    cudaFuncSetAttribute(score_kernel,
                         cudaFuncAttributeMaxDynamicSharedMemorySize, SC_SMEM);
    score_kernel<<<256, 256, SC_SMEM>>>(mlp_w, mlp_b, out);

    topk_kernel<<<BATCH * NODES / 8, 256>>>(out);
}